// round 1
// baseline (speedup 1.0000x reference)
#include <cuda_runtime.h>

// Problem constants (fixed by the dataset)
#define NB_B 64
#define NB_N 20000
#define NB_E 1280000

// Scratch: x transposed to [N, B] (node-major) and the accumulator [N, B].
// 5.12 MB each — both L2-resident during the edge kernel.
__device__ __align__(16) float g_xT[NB_N * NB_B];
__device__ __align__(16) float g_acc[NB_N * NB_B];

// ---------------------------------------------------------------------------
// Kernel 1: transpose x [B, N] -> g_xT [N, B], and zero g_acc.
// 32x32 shared-memory tiles, fully coalesced on both sides.
// N = 20000 = 625 * 32, B = 64 = 2 * 32 -> no bounds checks needed.
// ---------------------------------------------------------------------------
__global__ void prep_kernel(const float* __restrict__ x) {
    __shared__ float tile[32][33];
    const int n0 = blockIdx.x * 32;
    const int b0 = blockIdx.y * 32;
    const int tx = threadIdx.x, ty = threadIdx.y;

    // coalesced read of x[b0+ty][n0+tx]
    tile[ty][tx] = x[(b0 + ty) * NB_N + (n0 + tx)];
    __syncthreads();

    // coalesced write of xT[n0+ty][b0+tx]
    const int idx = (n0 + ty) * NB_B + (b0 + tx);
    g_xT[idx] = tile[tx][ty];
    g_acc[idx] = 0.0f;
}

// ---------------------------------------------------------------------------
// Kernel 2: edge scatter. One half-warp (16 lanes) per edge.
// Each lane handles a float4 (4 of the 64 batch features):
//   gather 256B contiguous from g_xT[src], scale by adj*w,
//   vector-RED 16B into g_acc[dst].
// ---------------------------------------------------------------------------
__global__ void edge_kernel(const float* __restrict__ adj,
                            const float* __restrict__ w,
                            const int*   __restrict__ src,
                            const int*   __restrict__ dst) {
    const int t = blockIdx.x * blockDim.x + threadIdx.x;
    const int e = t >> 4;
    if (e >= NB_E) return;
    const int lane = t & 15;

    const float c = adj[e] * w[e];
    const int s = src[e];
    const int d = dst[e];

    const float4 v = reinterpret_cast<const float4*>(g_xT + (size_t)s * NB_B)[lane];
    float4 r;
    r.x = v.x * c; r.y = v.y * c; r.z = v.z * c; r.w = v.w * c;

    // sm_90+ vector atomic; result unused -> ptxas emits RED (no return trip)
    atomicAdd(reinterpret_cast<float4*>(g_acc + (size_t)d * NB_B) + lane, r);
}

// ---------------------------------------------------------------------------
// Kernel 3: epilogue. Transpose g_acc [N, B] -> out [B, N] while applying
//   out[b][n] = relu(acc[n][b] * (x[0][n] * self_w[n]) + bias[n])
// ---------------------------------------------------------------------------
__global__ void epilogue_kernel(const float* __restrict__ x,
                                const float* __restrict__ self_w,
                                const float* __restrict__ bias,
                                float* __restrict__ out) {
    __shared__ float tile[32][33];
    const int n0 = blockIdx.x * 32;
    const int b0 = blockIdx.y * 32;
    const int tx = threadIdx.x, ty = threadIdx.y;

    // coalesced read of acc[n0+ty][b0+tx]
    tile[ty][tx] = g_acc[(n0 + ty) * NB_B + (b0 + tx)];
    __syncthreads();

    const int n = n0 + tx;                 // same n across ty -> broadcast-friendly
    const float sl = x[n] * self_w[n];     // x row 0 (faithful reference quirk)
    const float o  = tile[tx][ty] * sl + bias[n];   // tile[tx][ty] = acc[n][b0+ty]
    out[(b0 + ty) * NB_N + n] = fmaxf(o, 0.0f);
}

// ---------------------------------------------------------------------------
// Launch
// ---------------------------------------------------------------------------
extern "C" void kernel_launch(void* const* d_in, const int* in_sizes, int n_in,
                              void* d_out, int out_size) {
    const float* x      = (const float*)d_in[0];
    const float* adj    = (const float*)d_in[1];
    const float* w      = (const float*)d_in[2];
    const float* self_w = (const float*)d_in[3];
    const float* bias   = (const float*)d_in[4];
    const int*   src    = (const int*)d_in[5];
    const int*   dst    = (const int*)d_in[6];
    float* out = (float*)d_out;

    dim3 tb(32, 32);
    dim3 tg(NB_N / 32, NB_B / 32);   // (625, 2)

    prep_kernel<<<tg, tb>>>(x);

    const int total_threads = NB_E * 16;          // half-warp per edge
    const int block = 256;
    edge_kernel<<<(total_threads + block - 1) / block, block>>>(adj, w, src, dst);

    epilogue_kernel<<<tg, tb>>>(x, self_w, bias, out);
}